// round 1
// baseline (speedup 1.0000x reference)
#include <cuda_runtime.h>
#include <math.h>

#define BATCH   128
#define CCH     16
#define TLEN    40000
#define DIMSEL  8
#define TSTART  6000
#define SEGLEN  8064     /* 14064 - 6000 */
#define KS      64
#define NWIN    8001     /* SEGLEN - KS + 1 */
#define EOUT    32
#define NT      512

__global__ __launch_bounds__(NT, 1)
void shapelet_kernel(const float* __restrict__ x,
                     const float* __restrict__ shp,
                     const float* __restrict__ l1_w,
                     const float* __restrict__ l1_b,
                     const float* __restrict__ l2_w,
                     const float* __restrict__ l2_b,
                     float* __restrict__ out)
{
    __shared__ float seg[SEGLEN];
    __shared__ float s[KS];
    __shared__ float s_mean_sh;
    __shared__ float redS[NT];
    __shared__ int   redI[NT];

    const int b   = blockIdx.x;
    const int tid = threadIdx.x;

    // ---- stage segment: x[b, DIMSEL, TSTART : TSTART+SEGLEN] ----
    const float* xb = x + ((size_t)b * CCH + DIMSEL) * TLEN + TSTART;
    // element offset = (16b+8)*40000 + 6000, multiple of 4 -> float4 aligned
    const float4* xb4 = (const float4*)xb;
    #pragma unroll 4
    for (int i = tid; i < SEGLEN / 4; i += NT) {
        ((float4*)seg)[i] = xb4[i];
    }
    if (tid < KS) s[tid] = shp[tid];
    __syncthreads();

    if (tid == 0) {
        float sm = 0.f;
        #pragma unroll
        for (int k = 0; k < KS; k++) sm += s[k];
        s_mean_sh = sm * (1.0f / KS);
    }
    __syncthreads();
    const float s_mean = s_mean_sh;

    // ---- sliding correlation scores, strided window assignment ----
    float best = -INFINITY;
    int   bidx = NWIN;  // larger than any valid index
    for (int w = tid; w < NWIN; w += NT) {
        float dot = 0.f, sum = 0.f, sq = 0.f;
        #pragma unroll
        for (int k = 0; k < KS; k++) {
            float v = seg[w + k];
            dot = fmaf(v, s[k], dot);
            sum += v;
            sq  = fmaf(v, v, sq);
        }
        float num = dot - s_mean * sum;
        float den = sq - sum * sum * (1.0f / KS);
        float sc  = num * rsqrtf(den);
        if (sc > best) { best = sc; bidx = w; }  // strict > keeps lowest w
    }
    redS[tid] = best;
    redI[tid] = bidx;
    __syncthreads();

    // ---- block argmax with first-index tie-break (matches jnp.argmax) ----
    #pragma unroll
    for (int off = NT / 2; off > 0; off >>= 1) {
        if (tid < off) {
            float so = redS[tid + off];
            int   io = redI[tid + off];
            if (so > redS[tid] || (so == redS[tid] && io < redI[tid])) {
                redS[tid] = so;
                redI[tid] = io;
            }
        }
        __syncthreads();
    }
    const int widx = redI[0];

    // ---- tiny affine head: out = best@l1_w^T + l1_b - (s@l2_w^T + l2_b) ----
    if (tid < EOUT) {
        float acc = l1_b[tid] - l2_b[tid];
        const float* w1 = l1_w + tid * KS;
        const float* w2 = l2_w + tid * KS;
        #pragma unroll
        for (int k = 0; k < KS; k++) {
            acc = fmaf(seg[widx + k], w1[k], acc);
            acc = fmaf(-s[k],         w2[k], acc);
        }
        out[b * EOUT + tid] = acc;
    }
}

extern "C" void kernel_launch(void* const* d_in, const int* in_sizes, int n_in,
                              void* d_out, int out_size)
{
    const float* x    = (const float*)d_in[0];
    const float* shp  = (const float*)d_in[1];
    const float* l1_w = (const float*)d_in[2];
    const float* l1_b = (const float*)d_in[3];
    const float* l2_w = (const float*)d_in[4];
    const float* l2_b = (const float*)d_in[5];
    float* out = (float*)d_out;

    shapelet_kernel<<<BATCH, NT>>>(x, shp, l1_w, l1_b, l2_w, l2_b, out);
}

// round 4
// speedup vs baseline: 1.3126x; 1.3126x over previous
#include <cuda_runtime.h>
#include <math.h>

#define BATCH   128
#define CCH     16
#define TLEN    40000
#define DIMSEL  8
#define TSTART  6000
#define SEGLEN  8064     /* 14064 - 6000 */
#define KS      64
#define NWIN    8001     /* SEGLEN - KS + 1 */
#define EOUT    32
#define NT      512
#define WPT     17       /* windows per thread; odd -> gcd(17,32)=1, conflict-free */
#define SEGPAD  (NT * WPT + KS + 16)   /* 8704 + 80 = 8784; max read 511*17+79=8766 */

__global__ __launch_bounds__(NT, 1)
void shapelet_kernel(const float* __restrict__ x,
                     const float* __restrict__ shp,
                     const float* __restrict__ l1_w,
                     const float* __restrict__ l1_b,
                     const float* __restrict__ l2_w,
                     const float* __restrict__ l2_b,
                     float* __restrict__ out)
{
    __shared__ float seg[SEGPAD];
    __shared__ float ssh[KS];
    __shared__ float redS[NT];
    __shared__ int   redI[NT];

    const int b   = blockIdx.x;
    const int tid = threadIdx.x;

    // ---- stage segment: x[b, DIMSEL, TSTART : TSTART+SEGLEN] ----
    const float* xb = x + ((size_t)b * CCH + DIMSEL) * TLEN + TSTART;
    const float4* xb4 = (const float4*)xb;     // offset is multiple of 4 floats
    #pragma unroll 4
    for (int i = tid; i < SEGLEN / 4; i += NT) {
        ((float4*)seg)[i] = xb4[i];
    }
    // zero the tail pad so out-of-range windows compute garbage safely (NaN/0)
    for (int i = SEGLEN + tid; i < SEGPAD; i += NT) seg[i] = 0.f;
    if (tid < KS) ssh[tid] = shp[tid];
    __syncthreads();

    // ---- shapelet into registers, centered ----
    float sc[KS];
    float s_sum = 0.f;
    #pragma unroll
    for (int k = 0; k < KS; k++) { sc[k] = ssh[k]; s_sum += sc[k]; }
    const float s_mean = s_sum * (1.0f / KS);
    #pragma unroll
    for (int k = 0; k < KS; k++) sc[k] -= s_mean;

    // ---- streaming dot products: 17 contiguous windows per thread ----
    const int base = tid * WPT;
    float dot[WPT];
    #pragma unroll
    for (int i = 0; i < WPT; i++) dot[i] = 0.f;

    #pragma unroll
    for (int j = 0; j < KS + WPT - 1; j++) {      // 80 values, each loaded once
        const float v = seg[base + j];
        #pragma unroll
        for (int w = 0; w < WPT; w++) {
            const int k = j - w;                  // compile-time after unroll
            if (k >= 0 && k < KS)
                dot[w] = fmaf(v, sc[k], dot[w]);
        }
    }

    // ---- sliding sum / sumsq + scores ----
    float best = -INFINITY;
    int   bidx = NWIN;
    float sum = 0.f, sq = 0.f;
    #pragma unroll
    for (int j = 0; j < KS; j++) {
        const float v = seg[base + j];
        sum += v;
        sq   = fmaf(v, v, sq);
    }
    #pragma unroll
    for (int i = 0; i < WPT; i++) {
        if (i > 0) {
            const float vo = seg[base + i - 1];
            const float vn = seg[base + i - 1 + KS];
            sum += vn - vo;
            sq  += fmaf(vn, vn, -vo * vo);
        }
        const float den = sq - sum * sum * (1.0f / KS);
        const float scv = dot[i] * rsqrtf(den);   // NaN for padded windows -> never wins
        const int   w   = base + i;
        if (w < NWIN && scv > best) { best = scv; bidx = w; }  // strict > : lowest index
    }
    redS[tid] = best;
    redI[tid] = bidx;
    __syncthreads();

    // ---- block argmax, first-index tie-break ----
    #pragma unroll
    for (int off = NT / 2; off > 0; off >>= 1) {
        if (tid < off) {
            const float so = redS[tid + off];
            const int   io = redI[tid + off];
            if (so > redS[tid] || (so == redS[tid] && io < redI[tid])) {
                redS[tid] = so;
                redI[tid] = io;
            }
        }
        __syncthreads();
    }
    const int widx = redI[0];

    // ---- tiny affine head ----
    if (tid < EOUT) {
        float acc = l1_b[tid] - l2_b[tid];
        const float* w1 = l1_w + tid * KS;
        const float* w2 = l2_w + tid * KS;
        #pragma unroll
        for (int k = 0; k < KS; k++) {
            acc = fmaf(seg[widx + k], w1[k], acc);
            acc = fmaf(-ssh[k],       w2[k], acc);
        }
        out[b * EOUT + tid] = acc;
    }
}

extern "C" void kernel_launch(void* const* d_in, const int* in_sizes, int n_in,
                              void* d_out, int out_size)
{
    const float* x    = (const float*)d_in[0];
    const float* shp  = (const float*)d_in[1];
    const float* l1_w = (const float*)d_in[2];
    const float* l1_b = (const float*)d_in[3];
    const float* l2_w = (const float*)d_in[4];
    const float* l2_b = (const float*)d_in[5];
    float* out = (float*)d_out;

    shapelet_kernel<<<BATCH, NT>>>(x, shp, l1_w, l1_b, l2_w, l2_b, out);
}

// round 5
// speedup vs baseline: 1.3516x; 1.0297x over previous
#include <cuda_runtime.h>
#include <math.h>

#define BATCH   128
#define CCH     16
#define TLEN    40000
#define DIMSEL  8
#define TSTART  6000
#define SEGLEN  8064     /* 14064 - 6000 */
#define KS      64
#define NWIN    8001     /* SEGLEN - KS + 1 */
#define EOUT    32
#define NT      1024
#define WPT     9        /* odd -> gcd(9,32)=1, conflict-free stride */
#define CHK     16       /* shapelet chunk held in registers */
#define NCHK    (KS / CHK)
#define SEGPAD  (NT * WPT + KS + 16)   /* 9296; max index read = 9278 */

__global__ __launch_bounds__(NT, 1)
void shapelet_kernel(const float* __restrict__ x,
                     const float* __restrict__ shp,
                     const float* __restrict__ l1_w,
                     const float* __restrict__ l1_b,
                     const float* __restrict__ l2_w,
                     const float* __restrict__ l2_b,
                     float* __restrict__ out)
{
    __shared__ float seg[SEGPAD];
    __shared__ float ssh_raw[KS];
    __shared__ float ssh_c[KS];     /* centered shapelet */
    __shared__ float s_mean_sh;
    __shared__ float redS[NT / 32];
    __shared__ int   redI[NT / 32];
    __shared__ int   widx_sh;

    const int b    = blockIdx.x;
    const int tid  = threadIdx.x;
    const int lane = tid & 31;
    const int wid  = tid >> 5;

    // ---- stage segment: x[b, DIMSEL, TSTART : TSTART+SEGLEN] ----
    const float* xb = x + ((size_t)b * CCH + DIMSEL) * TLEN + TSTART;
    const float4* xb4 = (const float4*)xb;       // element offset % 4 == 0
    #pragma unroll
    for (int i = tid; i < SEGLEN / 4; i += NT) {
        ((float4*)seg)[i] = xb4[i];
    }
    for (int i = SEGLEN + tid; i < SEGPAD; i += NT) seg[i] = 0.f;
    if (tid < KS) ssh_raw[tid] = shp[tid];
    __syncthreads();

    if (tid == 0) {
        float sm = 0.f;
        #pragma unroll
        for (int k = 0; k < KS; k++) sm += ssh_raw[k];
        s_mean_sh = sm * (1.0f / KS);
    }
    __syncthreads();
    if (tid < KS) ssh_c[tid] = ssh_raw[tid] - s_mean_sh;
    __syncthreads();

    // ---- streaming centered dot products: 9 contiguous windows / thread,
    //      shapelet processed in 4 register chunks of 16 ----
    const int base = tid * WPT;
    float dot[WPT];
    #pragma unroll
    for (int i = 0; i < WPT; i++) dot[i] = 0.f;

    #pragma unroll
    for (int c = 0; c < NCHK; c++) {
        float scc[CHK];
        #pragma unroll
        for (int m = 0; m < CHK; m++) scc[m] = ssh_c[c * CHK + m];  // broadcast LDS

        #pragma unroll
        for (int j = 0; j < CHK + WPT - 1; j++) {   // 24 values, each loaded once
            const float v = seg[base + c * CHK + j];
            #pragma unroll
            for (int i = 0; i < WPT; i++) {
                const int k = j - i;                // compile-time after unroll
                if (k >= 0 && k < CHK)
                    dot[i] = fmaf(v, scc[k], dot[i]);
            }
        }
    }

    // ---- sliding sum / sumsq + scores ----
    float best = -INFINITY;
    int   bidx = NWIN;
    float sum = 0.f, sq = 0.f;
    #pragma unroll
    for (int j = 0; j < KS; j++) {
        const float v = seg[base + j];
        sum += v;
        sq   = fmaf(v, v, sq);
    }
    #pragma unroll
    for (int i = 0; i < WPT; i++) {
        if (i > 0) {
            const float vo = seg[base + i - 1];
            const float vn = seg[base + i - 1 + KS];
            sum += vn - vo;
            sq  += fmaf(vn, vn, -vo * vo);
        }
        const float den = sq - sum * sum * (1.0f / KS);
        const float scv = dot[i] * rsqrtf(den);     // NaN on zero pad -> never wins
        const int   w   = base + i;
        if (w < NWIN && scv > best) { best = scv; bidx = w; }  // strict >
    }

    // ---- argmax: warp shfl reduce -> 32 partials -> warp 0 ----
    #pragma unroll
    for (int off = 16; off > 0; off >>= 1) {
        const float so = __shfl_xor_sync(0xffffffffu, best, off);
        const int   io = __shfl_xor_sync(0xffffffffu, bidx, off);
        if (so > best || (so == best && io < bidx)) { best = so; bidx = io; }
    }
    if (lane == 0) { redS[wid] = best; redI[wid] = bidx; }
    __syncthreads();

    if (wid == 0) {
        best = redS[lane];      // NT/32 == 32 entries, one per lane
        bidx = redI[lane];
        #pragma unroll
        for (int off = 16; off > 0; off >>= 1) {
            const float so = __shfl_xor_sync(0xffffffffu, best, off);
            const int   io = __shfl_xor_sync(0xffffffffu, bidx, off);
            if (so > best || (so == best && io < bidx)) { best = so; bidx = io; }
        }
        if (lane == 0) widx_sh = bidx;
    }
    __syncthreads();
    const int widx = widx_sh;

    // ---- tiny affine head ----
    if (tid < EOUT) {
        float acc = l1_b[tid] - l2_b[tid];
        const float* w1 = l1_w + tid * KS;
        const float* w2 = l2_w + tid * KS;
        #pragma unroll
        for (int k = 0; k < KS; k++) {
            acc = fmaf(seg[widx + k], w1[k], acc);
            acc = fmaf(-ssh_raw[k],   w2[k], acc);
        }
        out[b * EOUT + tid] = acc;
    }
}

extern "C" void kernel_launch(void* const* d_in, const int* in_sizes, int n_in,
                              void* d_out, int out_size)
{
    const float* x    = (const float*)d_in[0];
    const float* shp  = (const float*)d_in[1];
    const float* l1_w = (const float*)d_in[2];
    const float* l1_b = (const float*)d_in[3];
    const float* l2_w = (const float*)d_in[4];
    const float* l2_b = (const float*)d_in[5];
    float* out = (float*)d_out;

    shapelet_kernel<<<BATCH, NT>>>(x, shp, l1_w, l1_b, l2_w, l2_b, out);
}

// round 6
// speedup vs baseline: 1.4545x; 1.0762x over previous
#include <cuda_runtime.h>
#include <math.h>

#define BATCH   128
#define CCH     16
#define TLEN    40000
#define DIMSEL  8
#define TSTART  6000
#define SEGLEN  8064     /* 14064 - 6000 */
#define KS      64
#define NWIN    8001     /* SEGLEN - KS + 1 */
#define EOUT    32
#define NT      512
#define WPT     17       /* gcd(17,32)=1 -> conflict-free scalar LDS */
#define SEGPAD  8776     /* max read: 511*17 + 81 = 8768 */

typedef unsigned long long ull;

#define FMA2(d, a, b, c) \
    asm("fma.rn.f32x2 %0, %1, %2, %3;" : "=l"(d) : "l"(a), "l"(b), "l"(c))
#define PACK2(d, lo, hi) \
    asm("mov.b64 %0, {%1, %2};" : "=l"(d) : "f"(lo), "f"(hi))
#define UNPACK2(lo, hi, s) \
    asm("mov.b64 {%0, %1}, %2;" : "=f"(lo), "=f"(hi) : "l"(s))

__global__ __launch_bounds__(NT, 1)
void shapelet_kernel(const float* __restrict__ x,
                     const float* __restrict__ shp,
                     const float* __restrict__ l1_w,
                     const float* __restrict__ l1_b,
                     const float* __restrict__ l2_w,
                     const float* __restrict__ l2_b,
                     float* __restrict__ out)
{
    __shared__ float  seg[SEGPAD];
    __shared__ float  ssh_raw[KS];
    __shared__ float  ssh_c[KS + 1];         /* centered; [64] = 0 pad */
    __shared__ float2 p2sh[KS];              /* p2sh[k] = (sc[k], sc[k+1]) */
    __shared__ float  s_mean_sh;
    __shared__ float  redS[NT / 32];
    __shared__ int    redI[NT / 32];
    __shared__ int    widx_sh;

    const int b    = blockIdx.x;
    const int tid  = threadIdx.x;
    const int lane = tid & 31;
    const int wid  = tid >> 5;

    // ---- stage segment ----
    const float* xb = x + ((size_t)b * CCH + DIMSEL) * TLEN + TSTART;
    const float4* xb4 = (const float4*)xb;           // offset % 4 floats == 0
    #pragma unroll
    for (int i = tid; i < SEGLEN / 4; i += NT)
        ((float4*)seg)[i] = xb4[i];
    for (int i = SEGLEN + tid; i < SEGPAD; i += NT) seg[i] = 0.f;
    if (tid < KS) ssh_raw[tid] = shp[tid];
    __syncthreads();

    if (tid == 0) {
        float sm = 0.f;
        #pragma unroll
        for (int k = 0; k < KS; k++) sm += ssh_raw[k];
        s_mean_sh = sm * (1.0f / KS);
        ssh_c[KS] = 0.f;
    }
    __syncthreads();
    if (tid < KS) ssh_c[tid] = ssh_raw[tid] - s_mean_sh;
    __syncthreads();
    if (tid < KS) p2sh[tid] = make_float2(ssh_c[tid], ssh_c[tid + 1]);
    __syncthreads();

    // ---- packed streaming dots: 17 windows/thread, j-tap pairs via FFMA2 ----
    const int base = tid * WPT;
    ull dot2[WPT];
    #pragma unroll
    for (int i = 0; i < WPT; i++) dot2[i] = 0ull;
    ull sum2 = 0ull, sq2 = 0ull;
    ull ONES; { PACK2(ONES, 1.0f, 1.0f); }

    // chunk c covers shapelet-pair indices k in [16c, 16c+16)
    #pragma unroll
    for (int c = 0; c < 4; c++) {
        ull p2r[16];
        #pragma unroll
        for (int m = 0; m < 16; m++)
            p2r[m] = *(const ull*)&p2sh[16 * c + m];   // broadcast LDS.64

        // jj range for this chunk: [8c, 8c+16]
        #pragma unroll
        for (int t = 0; t <= 16; t++) {
            const int jj = 8 * c + t;
            const float v0 = seg[base + 2 * jj];
            const float v1 = seg[base + 2 * jj + 1];
            ull vp; PACK2(vp, v0, v1);

            // fused sum/sumsq over j = 0..63 (jj < 32), each jj counted once
            if (((c == 0) || (t >= 9)) && (jj < 32)) {
                FMA2(sum2, vp, ONES, sum2);
                FMA2(sq2,  vp, vp,   sq2);
            }

            #pragma unroll
            for (int i = 0; i < WPT; i++) {
                const int k = 2 * jj - i;             // compile-time
                if (k >= 16 * c && k < 16 * c + 16)
                    FMA2(dot2[i], vp, p2r[k - 16 * c], dot2[i]);
            }
        }
    }

    // odd windows: leading edge pair k = -1 -> multiplier (0, sc[0])
    {
        ull edge; PACK2(edge, 0.0f, ssh_c[0]);
        #pragma unroll
        for (int i = 1; i < WPT; i += 2) {
            const int jj = (i - 1) / 2;
            const float v0 = seg[base + 2 * jj];
            const float v1 = seg[base + 2 * jj + 1];
            ull vp; PACK2(vp, v0, v1);
            FMA2(dot2[i], vp, edge, dot2[i]);
        }
    }

    // ---- scores with sliding sum/sumsq ----
    float sum, sq;
    {
        float a, bb;
        UNPACK2(a, bb, sum2); sum = a + bb;
        UNPACK2(a, bb, sq2);  sq  = a + bb;
    }
    float best = -INFINITY;
    int   bidx = NWIN;
    #pragma unroll
    for (int i = 0; i < WPT; i++) {
        if (i > 0) {
            const float vo = seg[base + i - 1];
            const float vn = seg[base + i - 1 + KS];
            sum += vn - vo;
            sq  += fmaf(vn, vn, -vo * vo);
        }
        float dlo, dhi;
        UNPACK2(dlo, dhi, dot2[i]);
        const float dot = dlo + dhi;
        const float den = sq - sum * sum * (1.0f / KS);
        const float scv = dot * rsqrtf(den);          // NaN/garbage on pad: guarded
        const int   w   = base + i;
        if (w < NWIN && scv > best) { best = scv; bidx = w; }   // strict > : lowest idx
    }

    // ---- argmax: warp shfl -> cross-warp ----
    #pragma unroll
    for (int off = 16; off > 0; off >>= 1) {
        const float so = __shfl_xor_sync(0xffffffffu, best, off);
        const int   io = __shfl_xor_sync(0xffffffffu, bidx, off);
        if (so > best || (so == best && io < bidx)) { best = so; bidx = io; }
    }
    if (lane == 0) { redS[wid] = best; redI[wid] = bidx; }
    __syncthreads();

    if (wid == 0) {
        best = (lane < NT / 32) ? redS[lane] : -INFINITY;
        bidx = (lane < NT / 32) ? redI[lane] : NWIN;
        #pragma unroll
        for (int off = 16; off > 0; off >>= 1) {
            const float so = __shfl_xor_sync(0xffffffffu, best, off);
            const int   io = __shfl_xor_sync(0xffffffffu, bidx, off);
            if (so > best || (so == best && io < bidx)) { best = so; bidx = io; }
        }
        if (lane == 0) widx_sh = bidx;
    }
    __syncthreads();
    const int widx = widx_sh;

    // ---- tiny affine head ----
    if (tid < EOUT) {
        float acc = l1_b[tid] - l2_b[tid];
        const float* w1 = l1_w + tid * KS;
        const float* w2 = l2_w + tid * KS;
        #pragma unroll
        for (int k = 0; k < KS; k++) {
            acc = fmaf(seg[widx + k], w1[k], acc);
            acc = fmaf(-ssh_raw[k],   w2[k], acc);
        }
        out[b * EOUT + tid] = acc;
    }
}

extern "C" void kernel_launch(void* const* d_in, const int* in_sizes, int n_in,
                              void* d_out, int out_size)
{
    const float* x    = (const float*)d_in[0];
    const float* shp  = (const float*)d_in[1];
    const float* l1_w = (const float*)d_in[2];
    const float* l1_b = (const float*)d_in[3];
    const float* l2_w = (const float*)d_in[4];
    const float* l2_b = (const float*)d_in[5];
    float* out = (float*)d_out;

    shapelet_kernel<<<BATCH, NT>>>(x, shp, l1_w, l1_b, l2_w, l2_b, out);
}